// round 1
// baseline (speedup 1.0000x reference)
#include <cuda_runtime.h>
#include <math.h>

#define Bsz 256
#define Dm  1024
#define Kg  7
#define VOCN 32000

// ---------------- scratch (static device allocations only) ----------------
__device__ float g_femb[Bsz * Dm];
__device__ float g_c[Bsz * Dm];       // perm space
__device__ float g_z0[Bsz * Dm];      // perm space
__device__ float g_z1[Bsz * Dm];      // perm space
__device__ float g_stabh[Bsz * Dm];
__device__ float g_gamma[Bsz];
__device__ int   g_ksel[Bsz];
__device__ int   g_perm[Bsz];         // perm[p] = b
__device__ int   g_pos[Bsz];          // pos[b]  = p
__device__ int   g_gstart[Kg + 1];
__device__ float g_normsq[40];
__device__ int   g_done;
__device__ int   g_zfinal;

// ---------------- helpers ----------------
__device__ __forceinline__ float blockSum(float v) {
    __shared__ float rb[256];
    int t = threadIdx.x;
    rb[t] = v;
    __syncthreads();
    #pragma unroll
    for (int s = 128; s > 0; s >>= 1) {
        if (t < s) rb[t] += rb[t + s];
        __syncthreads();
    }
    float r = rb[0];
    __syncthreads();
    return r;
}

// ---------------- K0: routing / embeddings / gamma / pi ----------------
__global__ void k_setup(const float* __restrict__ h, const float* __restrict__ fs,
                        const float* __restrict__ fe, const int* __restrict__ tok,
                        const float* __restrict__ opemb, const float* __restrict__ numw,
                        const float* __restrict__ numb, const float* __restrict__ addr,
                        const float* __restrict__ fsw, const float* __restrict__ fsb,
                        const float* __restrict__ few, const float* __restrict__ feb,
                        const float* __restrict__ c1w, const float* __restrict__ c1b,
                        const float* __restrict__ c2w, const float* __restrict__ c2b,
                        float* __restrict__ out_pi)
{
    __shared__ float s_te[Dm];
    __shared__ float s_f[Dm];
    __shared__ float s_sc[Kg];
    int b = blockIdx.x, t = threadIdx.x;
    int tk = tok[b];
    float sv = fs[b], ev = fe[b];

    for (int j = t; j < Dm; j += 256) {
        float f = tanhf(fsw[j] * sv + fsb[j] + few[j] * ev + feb[j]);
        s_f[j] = f;
        g_femb[b * Dm + j] = f;
        float te;
        if (tk >= 7) te = ((float)tk - 7.0f) * numw[j] + numb[j];
        else         te = opemb[min(tk, 6) * Dm + j];
        s_te[j] = te;
    }
    __syncthreads();

    float p1 = 0.f, p2 = 0.f;
    for (int j = t; j < Dm; j += 256) {
        float a = s_te[j];
        float c = a + s_f[j];
        p1 += a * a;
        p2 += c * c;
    }
    float n1 = sqrtf(blockSum(p1));
    float n2 = sqrtf(blockSum(p2));
    float inv1 = 1.0f / fmaxf(n1, 1e-12f);
    float inv2 = 1.0f / fmaxf(n2, 1e-12f);

    for (int k = 0; k < Kg; k++) {
        float d1 = 0.f, d2 = 0.f, na = 0.f;
        for (int j = t; j < Dm; j += 256) {
            float a = addr[k * Dm + j];
            float te = s_te[j];
            d1 += te * a;
            d2 += (te + s_f[j]) * a;
            na += a * a;
        }
        d1 = blockSum(d1);
        d2 = blockSum(d2);
        na = blockSum(na);
        if (t == 0) {
            float invA = 1.0f / fmaxf(sqrtf(na), 1e-12f);
            s_sc[k] = (tk < 7) ? d1 * inv1 * invA : d2 * inv2 * invA;
        }
    }
    __syncthreads();

    if (t == 0) {
        float m = -1e30f;
        #pragma unroll
        for (int k = 0; k < Kg; k++) m = fmaxf(m, 5.0f * s_sc[k]);
        float ex[Kg], sum = 0.f;
        #pragma unroll
        for (int k = 0; k < Kg; k++) { ex[k] = expf(5.0f * s_sc[k] - m); sum += ex[k]; }
        float inv = 1.0f / sum;
        float ent = 0.f, best = -1.f;
        int am = 0;
        #pragma unroll
        for (int k = 0; k < Kg; k++) {
            float p = ex[k] * inv;
            out_pi[b * Kg + k] = p;
            ent -= p * logf(p + 1e-8f);
            if (p > best) { best = p; am = k; }
        }
        g_ksel[b] = am;
        // ctrl MLP: [ent, 0] -> relu(16) -> softplus(1)
        float g = c2b[0];
        #pragma unroll
        for (int j = 0; j < 16; j++) {
            float hh = c1w[j * 2] * ent + c1b[j];
            hh = fmaxf(hh, 0.f);
            g += c2w[j] * hh;
        }
        g_gamma[b] = (g > 20.f) ? g : log1pf(expf(g));
    }
}

// ---------------- K0b: grouping + per-run state reset ----------------
__global__ void k_group()
{
    __shared__ int sk[Bsz];
    __shared__ int cnt[Kg];
    __shared__ int cur[Kg];
    int t = threadIdx.x;
    sk[t] = g_ksel[t];
    __syncthreads();
    if (t < Kg) {
        int c = 0;
        for (int b = 0; b < Bsz; b++) c += (sk[b] == t);
        cnt[t] = c;
    }
    __syncthreads();
    if (t == 0) {
        int s = 0;
        for (int k = 0; k < Kg; k++) { cur[k] = s; g_gstart[k] = s; s += cnt[k]; }
        g_gstart[Kg] = s;
        g_done = 0;
        g_zfinal = 0;   // z after 40 iters lands in buffer 0
    }
    __syncthreads();
    int myk = sk[t];
    int rank = 0;
    for (int b = 0; b < t; b++) rank += (sk[b] == myk);
    int p = cur[myk] + rank;
    g_perm[p] = t;
    g_pos[t] = p;
    if (t < 40) g_normsq[t] = 0.f;
}

// ---------------- grouped NN GEMM (rows grouped by gremlin) ----------------
// out[r,:] = ACT( A[r,:] @ Mats[g] (+ c[r,:]) )  for rows r of group g
// AS: 0=Aext(b-space if GATHER), 1=g_z0, 2=g_z1, 3=g_femb
// OS: 0=g_c, 1=g_z0, 2=g_z1
template<bool GATHER, bool ZEROA, bool ADDC, bool DOTANH, bool DONORM, bool DONECHK,
         int AS, int OS>
__global__ void k_grouped(const float* __restrict__ Aext, const float* __restrict__ Mats,
                          int iter)
{
    if (DONECHK) { if (g_done) return; }
    int g = blockIdx.z;
    int gs = g_gstart[g];
    int Mg = g_gstart[g + 1] - gs;
    int rt = blockIdx.y;
    if (rt * 32 >= Mg) return;
    int et = blockIdx.x;
    int tid = threadIdx.x;

    const float* Ap = (AS == 0) ? Aext : (AS == 1) ? g_z0 : (AS == 2) ? g_z1 : g_femb;
    float* Op = (OS == 0) ? g_c : (OS == 1) ? g_z0 : g_z1;
    const float* __restrict__ Wk = Mats + (size_t)g * Dm * Dm;

    __shared__ float As[32][16];
    __shared__ float Bs[16][68];
    float acc[8] = {0.f, 0.f, 0.f, 0.f, 0.f, 0.f, 0.f, 0.f};
    int r0 = (tid >> 4) << 1;     // 0..30
    int c0 = (tid & 15) << 2;     // 0..60

    if (!ZEROA) {
        int lr = tid >> 3;          // 0..31
        int lk = (tid & 7) << 1;    // 0..14
        bool arowValid = (rt * 32 + lr) < Mg;
        size_t abase = 0;
        if (arowValid) {
            int rr = gs + rt * 32 + lr;
            int grow = GATHER ? g_perm[rr] : rr;
            abase = (size_t)grow * Dm + lk;
        }
        int bk = tid >> 4;          // 0..15
        int be = (tid & 15) << 2;   // 0..60
        size_t bbase = (size_t)bk * Dm + et * 64 + be;

        for (int k0 = 0; k0 < Dm; k0 += 16) {
            float2 av = make_float2(0.f, 0.f);
            if (arowValid) av = *(const float2*)(Ap + abase + k0);
            As[lr][lk] = av.x;
            As[lr][lk + 1] = av.y;
            float4 bv = *(const float4*)(Wk + bbase + (size_t)k0 * Dm);
            *(float4*)&Bs[bk][be] = bv;
            __syncthreads();
            #pragma unroll
            for (int kk = 0; kk < 16; kk++) {
                float a0 = As[r0][kk], a1 = As[r0 + 1][kk];
                float4 bb = *(const float4*)&Bs[kk][c0];
                acc[0] += a0 * bb.x; acc[1] += a0 * bb.y;
                acc[2] += a0 * bb.z; acc[3] += a0 * bb.w;
                acc[4] += a1 * bb.x; acc[5] += a1 * bb.y;
                acc[6] += a1 * bb.z; acc[7] += a1 * bb.w;
            }
            __syncthreads();
        }
    }

    float nsum = 0.f;
    int ebase = et * 64 + c0;
    #pragma unroll
    for (int i = 0; i < 2; i++) {
        int rloc = rt * 32 + r0 + i;
        if (rloc < Mg) {
            size_t rr = gs + rloc;
            #pragma unroll
            for (int j = 0; j < 4; j++) {
                float v = acc[i * 4 + j];
                if (ADDC) v += g_c[rr * Dm + ebase + j];
                if (DOTANH) v = tanhf(v);
                if (DONORM) {
                    float zp = ZEROA ? 0.f : Ap[rr * Dm + ebase + j];
                    float d = v - zp;
                    nsum += d * d;
                }
                Op[rr * Dm + ebase + j] = v;
            }
        }
    }
    if (DONORM) {
        float tot = blockSum(nsum);
        if (tid == 0) atomicAdd(&g_normsq[iter], tot);
    }
}

// ---------------- convergence flag ----------------
__global__ void k_flag(int iter)
{
    if (g_done) return;
    if (g_normsq[iter] < 1e-8f) {   // ||zn - z||_F < 1e-4
        g_done = 1;
        g_zfinal = (iter + 1) & 1;
    }
}

// ---------------- NT GEMM: C = A[MxK] @ B[NxK]^T, K contiguous both ----------------
// EPI 0: g_stabh = tanh(acc + bias)
// EPI 1: Out = Hin + gamma * sigmoid(acc + bias) * z_star   (h_next)
// EPI 2: Out = acc + bias                                   (logits)
template<int EPI, bool CONCAT, bool A_STABH>
__global__ void k_nt(const float* __restrict__ Aext, const float* __restrict__ Bm,
                     const float* __restrict__ bias, float* __restrict__ Out,
                     const float* __restrict__ Hin, int Kdim, int N)
{
    __shared__ float Ast[16][68];
    __shared__ float Bst[16][68];
    int tid = threadIdx.x;
    int n0 = blockIdx.x * 64;
    int m0 = blockIdx.y * 64;
    const float* Ap = A_STABH ? g_stabh : Aext;

    float acc[16];
    #pragma unroll
    for (int i = 0; i < 16; i++) acc[i] = 0.f;

    int r0 = (tid >> 4) << 2;   // 0..60
    int c0 = (tid & 15) << 2;   // 0..60
    int alr = tid >> 2;         // 0..63
    int alk = (tid & 3) << 2;   // 0,4,8,12

    for (int k0 = 0; k0 < Kdim; k0 += 16) {
        float4 av;
        if (CONCAT) {
            int i = k0 + alk;
            if (i < Dm) av = *(const float4*)(Ap + (size_t)(m0 + alr) * Dm + i);
            else        av = *(const float4*)(g_femb + (size_t)(m0 + alr) * Dm + (i - Dm));
        } else {
            av = *(const float4*)(Ap + (size_t)(m0 + alr) * Kdim + k0 + alk);
        }
        Ast[alk + 0][alr] = av.x; Ast[alk + 1][alr] = av.y;
        Ast[alk + 2][alr] = av.z; Ast[alk + 3][alr] = av.w;
        float4 bv = *(const float4*)(Bm + (size_t)(n0 + alr) * Kdim + k0 + alk);
        Bst[alk + 0][alr] = bv.x; Bst[alk + 1][alr] = bv.y;
        Bst[alk + 2][alr] = bv.z; Bst[alk + 3][alr] = bv.w;
        __syncthreads();
        #pragma unroll
        for (int kk = 0; kk < 16; kk++) {
            float4 a = *(const float4*)&Ast[kk][r0];
            float4 b = *(const float4*)&Bst[kk][c0];
            acc[0]  += a.x * b.x; acc[1]  += a.x * b.y; acc[2]  += a.x * b.z; acc[3]  += a.x * b.w;
            acc[4]  += a.y * b.x; acc[5]  += a.y * b.y; acc[6]  += a.y * b.z; acc[7]  += a.y * b.w;
            acc[8]  += a.z * b.x; acc[9]  += a.z * b.y; acc[10] += a.z * b.z; acc[11] += a.z * b.w;
            acc[12] += a.w * b.x; acc[13] += a.w * b.y; acc[14] += a.w * b.z; acc[15] += a.w * b.w;
        }
        __syncthreads();
    }

    #pragma unroll
    for (int i = 0; i < 4; i++) {
        int m = m0 + r0 + i;
        #pragma unroll
        for (int j = 0; j < 4; j++) {
            int n = n0 + c0 + j;
            float v = acc[i * 4 + j] + bias[n];
            if (EPI == 0) {
                g_stabh[(size_t)m * Dm + n] = tanhf(v);
            } else if (EPI == 1) {
                float al = 1.f / (1.f + expf(-v));
                const float* zb = g_zfinal ? g_z1 : g_z0;
                float zs = zb[(size_t)g_pos[m] * Dm + n];
                Out[(size_t)m * Dm + n] = Hin[(size_t)m * Dm + n] + g_gamma[m] * al * zs;
            } else {
                Out[(size_t)m * N + n] = v;
            }
        }
    }
}

// ---------------- host ----------------
extern "C" void kernel_launch(void* const* d_in, const int* in_sizes, int n_in,
                              void* d_out, int out_size)
{
    const float* h      = (const float*)d_in[0];
    const float* fs     = (const float*)d_in[1];
    const float* fe     = (const float*)d_in[2];
    const int*   tok    = (const int*)  d_in[3];
    const float* opemb  = (const float*)d_in[4];
    const float* numw   = (const float*)d_in[5];
    const float* numb   = (const float*)d_in[6];
    const float* addr   = (const float*)d_in[7];
    const float* W      = (const float*)d_in[8];
    const float* U      = (const float*)d_in[9];
    const float* V      = (const float*)d_in[10];
    const float* fsw    = (const float*)d_in[11];
    const float* fsb    = (const float*)d_in[12];
    const float* few    = (const float*)d_in[13];
    const float* feb    = (const float*)d_in[14];
    const float* s1w    = (const float*)d_in[15];
    const float* s1b    = (const float*)d_in[16];
    const float* s2w    = (const float*)d_in[17];
    const float* s2b    = (const float*)d_in[18];
    const float* c1w    = (const float*)d_in[19];
    const float* c1b    = (const float*)d_in[20];
    const float* c2w    = (const float*)d_in[21];
    const float* c2b    = (const float*)d_in[22];
    const float* decw   = (const float*)d_in[23];
    const float* decb   = (const float*)d_in[24];

    float* out        = (float*)d_out;
    float* out_h      = out;                                   // [256,1024]
    float* out_logits = out + (size_t)Bsz * Dm;                // [256,32000]
    float* out_pi     = out + (size_t)Bsz * Dm + (size_t)Bsz * VOCN; // [256,7]

    // routing / embeddings / gamma / pi
    k_setup<<<Bsz, 256>>>(h, fs, fe, tok, opemb, numw, numb, addr,
                          fsw, fsb, few, feb, c1w, c1b, c2w, c2b, out_pi);
    k_group<<<1, 256>>>();

    dim3 gg(16, 8, Kg);
    // c = gather(h) @ U[k]
    k_grouped<true, false, false, false, false, false, 0, 0><<<gg, 256>>>(h, U, 0);
    // c += gather(f_emb) @ V[k]
    k_grouped<true, false, true, false, false, false, 3, 0><<<gg, 256>>>(nullptr, V, 0);

    // DEQ iteration 0: z1 = tanh(c), norm = ||z1||
    k_grouped<false, true, true, true, true, true, 0, 2><<<gg, 256>>>(nullptr, W, 0);
    k_flag<<<1, 1>>>(0);
    // iterations 1..39: ping-pong, early-exit via g_done
    for (int i = 1; i < 40; i++) {
        if (i & 1)
            k_grouped<false, false, true, true, true, true, 2, 1><<<gg, 256>>>(nullptr, W, i);
        else
            k_grouped<false, false, true, true, true, true, 1, 2><<<gg, 256>>>(nullptr, W, i);
        k_flag<<<1, 1>>>(i);
    }

    // stab_h = tanh([h, f_emb] @ stab1_w^T + b1)
    k_nt<0, true, false><<<dim3(Dm / 64, Bsz / 64), 256>>>(h, s1w, s1b, nullptr, nullptr, 2 * Dm, Dm);
    // h_next = h + gamma * sigmoid(stab_h @ stab2_w^T + b2) * z_star
    k_nt<1, false, true><<<dim3(Dm / 64, Bsz / 64), 256>>>(nullptr, s2w, s2b, out_h, h, Dm, Dm);
    // logits = h_next @ dec_w^T + dec_b
    k_nt<2, false, false><<<dim3(VOCN / 64, Bsz / 64), 256>>>(out_h, decw, decb, out_logits, nullptr, Dm, VOCN);
}